// round 1
// baseline (speedup 1.0000x reference)
#include <cuda_runtime.h>
#include <cuda_bf16.h>
#include <math.h>

#define BB 8
#define TT 512
#define DDIM 9
#define UPP 512
#define LL (TT * UPP)                 // 262144 samples per batch
#define SINE_N (BB * LL * DDIM)       // 18,874,368
#define UV_N   (BB * LL)              // 2,097,152
// out layout: [sine | uv | noise], total 39,845,888 floats

// Per-frame precomputed state (tiny: ~166 KB total)
__device__ float g_base[BB * DDIM * TT];  // frac(512 * exclusive frame prefix of rad_up)
__device__ float g_rad [BB * DDIM * TT];  // rad_up per frame (fp32, matches reference rounding)
__device__ float g_amp [BB * TT];         // noise amplitude per frame
__device__ float g_uvv [BB * TT];         // voiced flag per frame

// ---------------------------------------------------------------------------
// Kernel 1: per (b, harmonic) compute frame-level phase prefix in fp64.
// 72 blocks x 32 threads; each lane owns 16 frames, warp-scan stitches them.
// ---------------------------------------------------------------------------
__global__ void prep_kernel(const float* __restrict__ f0,
                            const float* __restrict__ rand_ini) {
    int bd = blockIdx.x;            // 0..71
    int b  = bd / DDIM;
    int d  = bd - b * DDIM;
    int lane = threadIdx.x;         // 0..31
    float mult = (float)(d + 1);

    float  radv[16];
    double excl[16];
    double ls = 0.0;

    #pragma unroll
    for (int k = 0; k < 16; k++) {
        int t = lane * 16 + k;
        float f = f0[b * TT + t];
        float r = (f * mult) / 48000.0f;          // fp32, matches jnp (always < 1)
        if (t == 0) r = fmodf(r + rand_ini[b * DDIM + d], 1.0f);  // rad_up[0]
        radv[k] = r;
        excl[k] = ls;                              // exclusive local prefix
        ls += (double)r;
    }

    // inclusive warp scan of per-lane totals (fp64)
    double inc = ls;
    #pragma unroll
    for (int s = 1; s < 32; s <<= 1) {
        double v = __shfl_up_sync(0xffffffffu, inc, s);
        if (lane >= s) inc += v;
    }
    double off = inc - ls;                         // exclusive warp offset

    #pragma unroll
    for (int k = 0; k < 16; k++) {
        int t = lane * 16 + k;
        double S  = off + excl[k];                 // exclusive frame prefix
        double ph = 512.0 * S;                     // phase at start of frame t
        ph -= floor(ph);                           // keep fractional part only
        g_base[(bd << 9) + t] = (float)ph;
        g_rad [(bd << 9) + t] = radv[k];
    }

    if (d == 0) {
        #pragma unroll
        for (int k = 0; k < 16; k++) {
            int t = lane * 16 + k;
            float f  = f0[b * TT + t];
            bool  v  = (f > 0.0f);
            g_uvv[b * TT + t] = v ? 1.0f : 0.0f;
            g_amp[b * TT + t] = v ? 0.003f : 0.033333333333333333f; // SINE_AMP/3
        }
    }
}

// ---------------------------------------------------------------------------
// Kernel 2: streaming pass. One thread per (b, l, d) element.
// Reads noise_randn once, writes sine and noise. Fully coalesced.
// ---------------------------------------------------------------------------
__global__ void __launch_bounds__(256)
sine_kernel(const float* __restrict__ nr, float* __restrict__ out) {
    unsigned idx = blockIdx.x * 256u + threadIdx.x;   // < SINE_N

    unsigned bl = idx / 9u;                 // b*L + l
    unsigned d  = idx - bl * 9u;            // harmonic index
    unsigned tg = bl >> 9;                  // b*T + t   (since L = T*512)
    unsigned j  = bl & 511u;                // sample within frame
    unsigned b  = bl >> 18;                 // batch (L = 2^18)
    unsigned t  = tg & 511u;

    unsigned pidx = ((b * 9u + d) << 9) | t;
    float r    = g_rad [pidx];
    float base = g_base[pidx];

    // exact fractional part of (j+1)*r + base
    float j1  = (float)(j + 1u);
    float p   = j1 * r;
    float plo = fmaf(j1, r, -p);            // exact product residual
    float pf  = p - floorf(p);              // exact (Sterbenz)
    float f   = pf + plo + base;
    f -= floorf(f);                         // f in [0,1)

    // sin(2*pi*f) = -sin(2*pi*(f-0.5)), arg in [-pi,pi) for MUFU accuracy
    float s = -0.1f * __sinf(6.283185307179586f * (f - 0.5f));

    float uvv = g_uvv[tg];
    float amp = g_amp[tg];
    float nz  = amp * nr[idx];

    out[idx] = s * uvv + nz;                         // sine_waves
    out[SINE_N + UV_N + idx] = nz;                   // noise
}

// ---------------------------------------------------------------------------
// Kernel 3: uv output, coalesced (1 float per (b,l)).
// ---------------------------------------------------------------------------
__global__ void __launch_bounds__(256)
uv_kernel(float* __restrict__ out) {
    unsigned bl = blockIdx.x * 256u + threadIdx.x;    // < UV_N
    out[SINE_N + bl] = g_uvv[bl >> 9];
}

extern "C" void kernel_launch(void* const* d_in, const int* in_sizes, int n_in,
                              void* d_out, int out_size) {
    const float* f0       = (const float*)d_in[0];
    const float* rand_ini = (const float*)d_in[1];
    const float* noise    = (const float*)d_in[2];
    float* out = (float*)d_out;

    prep_kernel<<<BB * DDIM, 32>>>(f0, rand_ini);
    sine_kernel<<<SINE_N / 256, 256>>>(noise, out);
    uv_kernel<<<UV_N / 256, 256>>>(out);
}

// round 4
// speedup vs baseline: 1.3599x; 1.3599x over previous
#include <cuda_runtime.h>
#include <cuda_bf16.h>
#include <math.h>

#define BB 8
#define TT 512
#define DDIM 9
#define UPP 512
#define LL (TT * UPP)                 // 262144 samples per batch
#define SINE_N (BB * LL * DDIM)       // 18,874,368
#define UV_N   (BB * LL)              // 2,097,152
// out layout: [sine | uv | noise]

// Interleaved per-frame tables (L2-resident, ~300 KB)
__device__ float2 g_rb[BB * DDIM * TT];  // {rad_up, frac(512 * exclusive frame prefix)}
__device__ float2 g_ua[BB * TT];         // {uv, noise_amp}

// ---------------------------------------------------------------------------
// Kernel 1: per (b, harmonic) frame-level fp64 phase prefix.
// 72 blocks x 512 threads; one frame per thread, block-level fp64 scan.
// ---------------------------------------------------------------------------
__global__ void __launch_bounds__(512)
sg_prep(const float* __restrict__ f0, const float* __restrict__ rand_ini) {
    __shared__ double warp_tot[16];

    int bd = blockIdx.x;            // 0..71
    int b  = bd / DDIM;
    int d  = bd - b * DDIM;
    int t  = threadIdx.x;           // 0..511 = frame index
    int wid  = t >> 5;
    int lane = t & 31;
    float mult = (float)(d + 1);

    float f = f0[b * TT + t];
    float r = (f * mult) / 48000.0f;                 // fp32, matches jnp rounding
    if (t == 0) r = fmodf(r + rand_ini[b * DDIM + d], 1.0f);
    double v = (double)r;

    // inclusive warp scan (fp64)
    double inc = v;
    #pragma unroll
    for (int s = 1; s < 32; s <<= 1) {
        double u = __shfl_up_sync(0xffffffffu, inc, s);
        if (lane >= s) inc += u;
    }
    if (lane == 31) warp_tot[wid] = inc;
    __syncthreads();

    // scan the 16 warp totals with a full warp (lanes >=16 read idx 15, ignored)
    if (wid == 0) {
        int i = lane < 15 ? lane : 15;
        double w = (lane < 16) ? warp_tot[i] : 0.0;
        double wi = w;
        #pragma unroll
        for (int s = 1; s < 16; s <<= 1) {
            double u = __shfl_up_sync(0xffffffffu, wi, s);
            if (lane >= s) wi += u;
        }
        if (lane < 16) warp_tot[lane] = wi;          // inclusive warp totals
    }
    __syncthreads();

    double excl = (inc - v) + (wid > 0 ? warp_tot[wid - 1] : 0.0);
    double ph = 512.0 * excl;
    ph -= floor(ph);                                 // fractional part

    g_rb[(bd << 9) + t] = make_float2(r, (float)ph);

    if (d == 0) {
        bool vo = (f > 0.0f);
        g_ua[b * TT + t] = make_float2(vo ? 1.0f : 0.0f,
                                       vo ? 0.003f : 0.033333333333333333f);
    }
}

// ---------------------------------------------------------------------------
// Kernel 2: streaming pass, 4 elements per thread (float4 I/O).
// ---------------------------------------------------------------------------
__global__ void __launch_bounds__(256)
sg_main(const float4* __restrict__ nr4, float4* __restrict__ sine4,
        float4* __restrict__ noise4) {
    unsigned q = blockIdx.x * 256u + threadIdx.x;    // < SINE_N/4
    unsigned idx0 = q * 4u;

    unsigned bl = idx0 / 9u;
    unsigned d  = idx0 - bl * 9u;

    float4 in4 = nr4[q];
    float nrv[4] = {in4.x, in4.y, in4.z, in4.w};
    float sv[4], nv[4];

    #pragma unroll
    for (int k = 0; k < 4; k++) {
        unsigned tg = bl >> 9;                       // b*T + t
        unsigned j  = bl & 511u;
        unsigned b  = bl >> 18;
        unsigned pidx = ((b * 9u + d) << 9) | (tg & 511u);

        float2 rb = g_rb[pidx];
        float r = rb.x, base = rb.y;

        // exact fractional part of (j+1)*r + base
        float j1  = (float)(j + 1u);
        float p   = j1 * r;
        float plo = fmaf(j1, r, -p);                 // exact product residual
        float pf  = p - floorf(p);
        float fph = pf + plo + base;
        fph -= floorf(fph);                          // [0,1)

        // sin(2*pi*f) = -sin(2*pi*(f-0.5)), arg in [-pi,pi)
        float s = -0.1f * __sinf(6.283185307179586f * (fph - 0.5f));

        float2 ua = g_ua[tg];
        float nz  = ua.y * nrv[k];
        sv[k] = s * ua.x + nz;
        nv[k] = nz;

        d++; if (d == 9u) { d = 0u; bl++; }
    }

    sine4[q]  = make_float4(sv[0], sv[1], sv[2], sv[3]);
    noise4[q] = make_float4(nv[0], nv[1], nv[2], nv[3]);
}

// ---------------------------------------------------------------------------
// Kernel 3: uv output, straight from f0 (no prep dependency), float4 stores.
// ---------------------------------------------------------------------------
__global__ void __launch_bounds__(256)
sg_uv(const float* __restrict__ f0, float4* __restrict__ uv4) {
    unsigned q = blockIdx.x * 256u + threadIdx.x;    // < UV_N/4
    unsigned tg = (q * 4u) >> 9;                     // same frame for all 4 (4 | 512)
    float u = (f0[tg] > 0.0f) ? 1.0f : 0.0f;
    uv4[q] = make_float4(u, u, u, u);
}

extern "C" void kernel_launch(void* const* d_in, const int* in_sizes, int n_in,
                              void* d_out, int out_size) {
    const float* f0       = (const float*)d_in[0];
    const float* rand_ini = (const float*)d_in[1];
    const float* noise    = (const float*)d_in[2];
    float* out = (float*)d_out;

    sg_prep<<<BB * DDIM, 512>>>(f0, rand_ini);
    sg_main<<<SINE_N / 4 / 256, 256>>>((const float4*)noise,
                                       (float4*)out,
                                       (float4*)(out + SINE_N + UV_N));
    sg_uv<<<UV_N / 4 / 256, 256>>>(f0, (float4*)(out + SINE_N));
}